// round 9
// baseline (speedup 1.0000x reference)
#include <cuda_runtime.h>
#include <cstdint>

// Problem constants
constexpr int B_  = 256;
constexpr int T_  = 512;
constexpr int H_  = 256;
constexpr int MTOT = B_ * T_;
constexpr size_t MH = (size_t)MTOT * H_;

// Scan decomposition: 16 batch groups x 8 column CTAs; 2 batch sub-groups of 8
constexpr int NC  = 8;
constexpr int HC  = 32;
constexpr int NBG = 16;
constexpr int NB  = 16;

// ---------------- device scratch ----------------
__device__ float g_xp[3 * MH];                 // projected inputs [gate][m][H]
__device__ float g_h [2][NBG][NB][H_];         // pre-decayed h, double-buffered
__device__ float g_rh[2][NBG][NB][H_];         // r*h_dec, double-buffered
// counters: [0]=rhA [1]=rhB [2]=hA [3]=hB ; per (group, producer CTA); 128B padded
__device__ unsigned g_cnt[4][NBG][NC][32];

// ---------------- f32x2 helpers ----------------
__device__ __forceinline__ unsigned long long pack2(float a, float b) {
    unsigned long long r;
    asm("mov.b64 %0, {%1,%2};" : "=l"(r) : "f"(a), "f"(b));
    return r;
}
__device__ __forceinline__ void fma2(unsigned long long& d, unsigned long long a, unsigned long long b) {
    asm("fma.rn.f32x2 %0, %1, %2, %0;" : "+l"(d) : "l"(a), "l"(b));
}
__device__ __forceinline__ unsigned long long add2(unsigned long long a, unsigned long long b) {
    unsigned long long r;
    asm("add.rn.f32x2 %0, %1, %2;" : "=l"(r) : "l"(a), "l"(b));
    return r;
}
__device__ __forceinline__ float fold2(unsigned long long v) {
    float lo, hi;
    asm("mov.b64 {%0,%1}, %2;" : "=f"(lo), "=f"(hi) : "l"(v));
    return lo + hi;
}

__device__ __forceinline__ float sigmoid_(float v) {
    float e = __expf(-v);
    return __fdividef(1.f, 1.f + e);
}
__device__ __forceinline__ float tanh_(float v) {
    float e = __expf(2.f * v);
    return __fdividef(e - 1.f, e + 1.f);
}

// ---------------- flag primitives ----------------
__device__ __forceinline__ void warp_arrive(unsigned* c) {
    asm volatile("red.release.gpu.global.add.u32 [%0], %1;" :: "l"(c), "r"(1u) : "memory");
}
__device__ __forceinline__ void poll_ge(const unsigned* f, unsigned need) {
    unsigned v;
    do {
        asm volatile("ld.acquire.gpu.global.u32 %0, [%1];" : "=r"(v) : "l"(f) : "memory");
    } while (v < need);
}

// ================= projection GEMM (proven, ~571us) =================
__global__ __launch_bounds__(256) void proj_kernel(
    const float* __restrict__ x,
    const float* __restrict__ Wz, const float* __restrict__ Wr, const float* __restrict__ Wh,
    const float* __restrict__ bz, const float* __restrict__ br, const float* __restrict__ bh)
{
    __shared__ float As[32 * 132];
    __shared__ float Bs[32 * 64];

    const int g = blockIdx.z;
    const float* W    = (g == 0) ? Wz : (g == 1) ? Wr : Wh;
    const float* bias = (g == 0) ? bz : (g == 1) ? br : bh;
    float* out = g_xp + (size_t)g * MH;

    const int mtile = blockIdx.x * 128;
    const int ntile = blockIdx.y * 64;
    const int tid = threadIdx.x;
    const int tm = tid >> 4;
    const int tn = tid & 15;

    float acc[8][4] = {};

    for (int kc = 0; kc < 128; kc += 32) {
        __syncthreads();
        #pragma unroll
        for (int it = 0; it < 4; ++it) {
            int idx = tid + it * 256;
            int m = idx >> 3, c4 = idx & 7;
            float4 v = *(const float4*)&x[(size_t)(mtile + m) * 128 + kc + c4 * 4];
            As[(c4 * 4 + 0) * 132 + m] = v.x;
            As[(c4 * 4 + 1) * 132 + m] = v.y;
            As[(c4 * 4 + 2) * 132 + m] = v.z;
            As[(c4 * 4 + 3) * 132 + m] = v.w;
        }
        #pragma unroll
        for (int it = 0; it < 2; ++it) {
            int idx = tid + it * 256;
            int kk = idx >> 4, n4 = idx & 15;
            float4 v = *(const float4*)&W[(size_t)(kc + kk) * 256 + ntile + n4 * 4];
            *(float4*)&Bs[kk * 64 + n4 * 4] = v;
        }
        __syncthreads();

        #pragma unroll
        for (int kk = 0; kk < 32; ++kk) {
            float4 a0 = *(const float4*)&As[kk * 132 + tm * 8];
            float4 a1 = *(const float4*)&As[kk * 132 + tm * 8 + 4];
            float4 bv = *(const float4*)&Bs[kk * 64 + tn * 4];
            float a[8] = {a0.x, a0.y, a0.z, a0.w, a1.x, a1.y, a1.z, a1.w};
            #pragma unroll
            for (int i = 0; i < 8; i++) {
                acc[i][0] += a[i] * bv.x;
                acc[i][1] += a[i] * bv.y;
                acc[i][2] += a[i] * bv.z;
                acc[i][3] += a[i] * bv.w;
            }
        }
    }

    float4 bb = *(const float4*)&bias[ntile + tn * 4];
    #pragma unroll
    for (int i = 0; i < 8; i++) {
        float4 o = make_float4(acc[i][0] + bb.x, acc[i][1] + bb.y,
                               acc[i][2] + bb.z, acc[i][3] + bb.w);
        *(float4*)&out[(size_t)(mtile + tm * 8 + i) * 256 + ntile + tn * 4] = o;
    }
}

// ================= reset: zero counters + g_h buffer 0 =================
__global__ void reset_kernel() {
    int i = blockIdx.x * 256 + threadIdx.x;
    if (i < NBG * NB * H_) ((float*)g_h)[i] = 0.f;
    if (i < 4 * NBG * NC * 32) ((unsigned*)g_cnt)[i] = 0;
}

// ================= persistent recurrent scan (batch-pipelined) =================
// Sub-group A = batch rows 0..7, B = rows 8..15. Each handoff of one sub-group
// is filled with the other sub-group's GEMM.
__global__ __launch_bounds__(256, 1) void scan_kernel(
    const float* __restrict__ Uz, const float* __restrict__ Ur, const float* __restrict__ Uh,
    const float* __restrict__ hdecay, float* __restrict__ out)
{
    extern __shared__ float sm[];
    float* asm_hA  = sm;             // [8][256] 8KB
    float* asm_hB  = sm + 2048;
    float* asm_rhA = sm + 4096;
    float* asm_rhB = sm + 6144;
    unsigned long long* redA_z = (unsigned long long*)(sm + 8192);   // [8][8][32] u64 16KB
    unsigned long long* redA_r = (unsigned long long*)(sm + 12288);
    unsigned long long* redB_z = (unsigned long long*)(sm + 16384);
    unsigned long long* redB_r = (unsigned long long*)(sm + 20480);

    const int tid = threadIdx.x;
    const int w = tid >> 5;          // warp -> k block [32w,32w+32), source CTA w
    const int l = tid & 31;
    const int grp = blockIdx.x >> 3;
    const int cg  = blockIdx.x & 7;
    const int j = cg * HC + l;
    const int b0g = grp * NB;

    // weights: packed f32x2 over k-pairs
    unsigned long long uz2[16], ur2[16], uh2[16];
    #pragma unroll
    for (int p = 0; p < 16; ++p) {
        int k = w * 32 + 2 * p;
        uz2[p] = pack2(Uz[(size_t)k * H_ + j], Uz[(size_t)(k + 1) * H_ + j]);
        ur2[p] = pack2(Ur[(size_t)k * H_ + j], Ur[(size_t)(k + 1) * H_ + j]);
        uh2[p] = pack2(Uh[(size_t)k * H_ + j], Uh[(size_t)(k + 1) * H_ + j]);
    }

    // flags: poll source CTA w's counters, publish own (cg)
    const unsigned* f_rhA = &g_cnt[0][grp][w][0];
    const unsigned* f_rhB = &g_cnt[1][grp][w][0];
    const unsigned* f_hA  = &g_cnt[2][grp][w][0];
    const unsigned* f_hB  = &g_cnt[3][grp][w][0];
    unsigned* my_rhA = &g_cnt[0][grp][cg][0];
    unsigned* my_rhB = &g_cnt[1][grp][cg][0];
    unsigned* my_hA  = &g_cnt[2][grp][cg][0];
    unsigned* my_hB  = &g_cnt[3][grp][cg][0];

    // gather mapping: lane l -> row l>>2 (0..7), 8 floats at col (l&3)*8
    const int gr = l >> 2;
    const int gc = (l & 3) * 8;

    // x projections for t=0 (row w = sub-group A; row w+8 = sub-group B)
    size_t mb0 = (size_t)(b0g + w) * T_;
    size_t mb1 = (size_t)(b0g + w + 8) * T_;
    float xzA = g_xp[mb0 * 256 + j],          xzB = g_xp[mb1 * 256 + j];
    float xrA = g_xp[MH + mb0 * 256 + j],     xrB = g_xp[MH + mb1 * 256 + j];
    float xhA = g_xp[2 * MH + mb0 * 256 + j], xhB = g_xp[2 * MH + mb1 * 256 + j];

    for (int t = 0; t < T_; ++t) {
        const int p  = t & 1;
        const int pn = (t + 1) & 1;
        const size_t m0 = (size_t)(b0g + w) * T_ + t;
        const size_t m1 = (size_t)(b0g + w + 8) * T_ + t;
        const bool more = (t + 1 < T_);

        float decA = 0.f, decB = 0.f;
        if (more) { decA = hdecay[m0 + 1]; decB = hdecay[m1 + 1]; }

        // ---- 1: gather hA (rows 0..7, own 32-col stripe) ----
        poll_ge(f_hA, 8u * (unsigned)t);
        {
            const float4* src = (const float4*)&g_h[p][grp][gr][w * 32 + gc];
            float4 v0 = __ldcg(src), v1 = __ldcg(src + 1);
            float4* dst = (float4*)&asm_hA[gr * 256 + w * 32 + gc];
            dst[0] = v0; dst[1] = v1;
        }
        __syncwarp();

        // ---- 2: merged z+r GEMM A ----
        #pragma unroll 1
        for (int b = 0; b < 8; ++b) {
            unsigned long long az0 = 0, az1 = 0, ar0 = 0, ar1 = 0;
            const float* hrow = &asm_hA[b * 256 + w * 32];
            #pragma unroll
            for (int q = 0; q < 8; ++q) {
                ulonglong2 hv = *(const ulonglong2*)(hrow + q * 4);
                fma2(az0, hv.x, uz2[2 * q]);
                fma2(az1, hv.y, uz2[2 * q + 1]);
                fma2(ar0, hv.x, ur2[2 * q]);
                fma2(ar1, hv.y, ur2[2 * q + 1]);
            }
            redA_z[(w * 8 + b) * 32 + l] = add2(az0, az1);
            redA_r[(w * 8 + b) * 32 + l] = add2(ar0, ar1);
        }

        // ---- 3: gather hB (rows 8..15) ----
        poll_ge(f_hB, 8u * (unsigned)t);
        {
            const float4* src = (const float4*)&g_h[p][grp][8 + gr][w * 32 + gc];
            float4 v0 = __ldcg(src), v1 = __ldcg(src + 1);
            float4* dst = (float4*)&asm_hB[gr * 256 + w * 32 + gc];
            dst[0] = v0; dst[1] = v1;
        }
        __syncthreads();   // S1

        // ---- 5: reduce rA, publish rhA (row w), per-warp flag ----
        float hdA = asm_hA[w * 256 + j];
        {
            unsigned long long s = 0;
            #pragma unroll
            for (int ww = 0; ww < 8; ++ww) s = add2(s, redA_r[(ww * 8 + w) * 32 + l]);
            float rA = sigmoid_(fold2(s) + xrA);
            __stcg(&g_rh[p][grp][w][j], rA * hdA);
        }
        __syncwarp();
        if (l == 0) warp_arrive(my_rhA);

        // ---- 6: merged z+r GEMM B (fills rhA handoff) ----
        #pragma unroll 1
        for (int b = 0; b < 8; ++b) {
            unsigned long long az0 = 0, az1 = 0, ar0 = 0, ar1 = 0;
            const float* hrow = &asm_hB[b * 256 + w * 32];
            #pragma unroll
            for (int q = 0; q < 8; ++q) {
                ulonglong2 hv = *(const ulonglong2*)(hrow + q * 4);
                fma2(az0, hv.x, uz2[2 * q]);
                fma2(az1, hv.y, uz2[2 * q + 1]);
                fma2(ar0, hv.x, ur2[2 * q]);
                fma2(ar1, hv.y, ur2[2 * q + 1]);
            }
            redB_z[(w * 8 + b) * 32 + l] = add2(az0, az1);
            redB_r[(w * 8 + b) * 32 + l] = add2(ar0, ar1);
        }
        __syncthreads();   // S2

        // ---- 8: reduce rB + publish rhB; reduce zA ----
        float hdB = asm_hB[w * 256 + j];
        {
            unsigned long long s = 0;
            #pragma unroll
            for (int ww = 0; ww < 8; ++ww) s = add2(s, redB_r[(ww * 8 + w) * 32 + l]);
            float rB = sigmoid_(fold2(s) + xrB);
            __stcg(&g_rh[p][grp][8 + w][j], rB * hdB);
        }
        __syncwarp();
        if (l == 0) warp_arrive(my_rhB);
        float zvA;
        {
            unsigned long long s = 0;
            #pragma unroll
            for (int ww = 0; ww < 8; ++ww) s = add2(s, redA_z[(ww * 8 + w) * 32 + l]);
            zvA = sigmoid_(fold2(s) + xzA);
        }

        // ---- 9: gather rhA (published at 5; filled by 6-8) ----
        poll_ge(f_rhA, 8u * (unsigned)(t + 1));
        {
            const float4* src = (const float4*)&g_rh[p][grp][gr][w * 32 + gc];
            float4 v0 = __ldcg(src), v1 = __ldcg(src + 1);
            float4* dst = (float4*)&asm_rhA[gr * 256 + w * 32 + gc];
            dst[0] = v0; dst[1] = v1;
        }
        __syncwarp();

        // ---- 10: h GEMM A (partials reuse redA_r; safe past S2) ----
        #pragma unroll 1
        for (int b = 0; b < 8; ++b) {
            unsigned long long ah0 = 0, ah1 = 0;
            const float* hrow = &asm_rhA[b * 256 + w * 32];
            #pragma unroll
            for (int q = 0; q < 8; ++q) {
                ulonglong2 hv = *(const ulonglong2*)(hrow + q * 4);
                fma2(ah0, hv.x, uh2[2 * q]);
                fma2(ah1, hv.y, uh2[2 * q + 1]);
            }
            redA_r[(w * 8 + b) * 32 + l] = add2(ah0, ah1);
        }
        __syncthreads();   // S3

        // ---- 12: reduce hA, combine, publish hA(t+1); out A ----
        {
            unsigned long long s = 0;
            #pragma unroll
            for (int ww = 0; ww < 8; ++ww) s = add2(s, redA_r[(ww * 8 + w) * 32 + l]);
            float hpA = tanh_(fold2(s) + xhA);
            float hA = (1.f - zvA) * hdA + zvA * hpA;
            if (more) __stcg(&g_h[pn][grp][w][j], hA * decA);
            __syncwarp();
            if (more && l == 0) warp_arrive(my_hA);
            out[m0 * 256 + j] = hA;
        }

        // ---- 13: reduce zB (fills rhB handoff) ----
        float zvB;
        {
            unsigned long long s = 0;
            #pragma unroll
            for (int ww = 0; ww < 8; ++ww) s = add2(s, redB_z[(ww * 8 + w) * 32 + l]);
            zvB = sigmoid_(fold2(s) + xzB);
        }

        // ---- 14: gather rhB ----
        poll_ge(f_rhB, 8u * (unsigned)(t + 1));
        {
            const float4* src = (const float4*)&g_rh[p][grp][8 + gr][w * 32 + gc];
            float4 v0 = __ldcg(src), v1 = __ldcg(src + 1);
            float4* dst = (float4*)&asm_rhB[gr * 256 + w * 32 + gc];
            dst[0] = v0; dst[1] = v1;
        }
        __syncwarp();

        // ---- 15: h GEMM B (partials reuse redB_r; safe past S3) ----
        #pragma unroll 1
        for (int b = 0; b < 8; ++b) {
            unsigned long long ah0 = 0, ah1 = 0;
            const float* hrow = &asm_rhB[b * 256 + w * 32];
            #pragma unroll
            for (int q = 0; q < 8; ++q) {
                ulonglong2 hv = *(const ulonglong2*)(hrow + q * 4);
                fma2(ah0, hv.x, uh2[2 * q]);
                fma2(ah1, hv.y, uh2[2 * q + 1]);
            }
            redB_r[(w * 8 + b) * 32 + l] = add2(ah0, ah1);
        }
        __syncthreads();   // S4

        // ---- 17: reduce hB, combine, publish hB(t+1); out B; x prefetch ----
        {
            unsigned long long s = 0;
            #pragma unroll
            for (int ww = 0; ww < 8; ++ww) s = add2(s, redB_r[(ww * 8 + w) * 32 + l]);
            float hpB = tanh_(fold2(s) + xhB);
            float hB = (1.f - zvB) * hdB + zvB * hpB;
            if (more) __stcg(&g_h[pn][grp][8 + w][j], hB * decB);
            __syncwarp();
            if (more && l == 0) warp_arrive(my_hB);
            out[m1 * 256 + j] = hB;
        }
        if (more) {
            xzA = g_xp[(m0 + 1) * 256 + j];          xzB = g_xp[(m1 + 1) * 256 + j];
            xrA = g_xp[MH + (m0 + 1) * 256 + j];     xrB = g_xp[MH + (m1 + 1) * 256 + j];
            xhA = g_xp[2 * MH + (m0 + 1) * 256 + j]; xhB = g_xp[2 * MH + (m1 + 1) * 256 + j];
        }
    }
}

// ================= launch =================
extern "C" void kernel_launch(void* const* d_in, const int* /*in_sizes*/, int /*n_in*/,
                              void* d_out, int /*out_size*/)
{
    const float* x      = (const float*)d_in[0];
    const float* hdecay = (const float*)d_in[1];
    const float* Wr = (const float*)d_in[2];
    const float* Wz = (const float*)d_in[3];
    const float* Wh = (const float*)d_in[4];
    const float* Ur = (const float*)d_in[5];
    const float* Uz = (const float*)d_in[6];
    const float* Uh = (const float*)d_in[7];
    const float* br = (const float*)d_in[8];
    const float* bz = (const float*)d_in[9];
    const float* bh = (const float*)d_in[10];
    float* out = (float*)d_out;

    constexpr int SMEM_SCAN = 24576 * 4;   // 96KB dynamic
    cudaFuncSetAttribute(scan_kernel, cudaFuncAttributeMaxDynamicSharedMemorySize, SMEM_SCAN);

    proj_kernel<<<dim3(MTOT / 128, H_ / 64, 3), 256>>>(x, Wz, Wr, Wh, bz, br, bh);
    reset_kernel<<<256, 256>>>();
    scan_kernel<<<NBG * NC, 256, SMEM_SCAN>>>(Uz, Ur, Uh, hdecay, out);
}

// round 11
// speedup vs baseline: 1.1484x; 1.1484x over previous
#include <cuda_runtime.h>
#include <cstdint>

// Problem constants
constexpr int B_  = 256;
constexpr int T_  = 512;
constexpr int H_  = 256;
constexpr int MTOT = B_ * T_;
constexpr size_t MH = (size_t)MTOT * H_;

// Scan decomposition: 16 batch groups x 8 column CTAs
constexpr int NC  = 8;
constexpr int HC  = 32;
constexpr int NBG = 16;
constexpr int NB  = 16;

// ---------------- device scratch ----------------
__device__ float g_xp[3 * MH];                 // projected inputs [gate][m][H]
__device__ float g_h [2][NBG][NB][H_];         // pre-decayed h, double-buffered
__device__ float g_rh[2][NBG][NB][H_];         // r*h_dec, double-buffered
__device__ unsigned g_cnt_rh[NBG][NC][32];     // per-producer counters (128B padded)
__device__ unsigned g_cnt_h [NBG][NC][32];

// ---------------- f32x2 helpers ----------------
__device__ __forceinline__ unsigned long long pack2(float a, float b) {
    unsigned long long r;
    asm("mov.b64 %0, {%1,%2};" : "=l"(r) : "f"(a), "f"(b));
    return r;
}
__device__ __forceinline__ void fma2(unsigned long long& d, unsigned long long a, unsigned long long b) {
    asm("fma.rn.f32x2 %0, %1, %2, %0;" : "+l"(d) : "l"(a), "l"(b));
}
__device__ __forceinline__ unsigned long long add2(unsigned long long a, unsigned long long b) {
    unsigned long long r;
    asm("add.rn.f32x2 %0, %1, %2;" : "=l"(r) : "l"(a), "l"(b));
    return r;
}
__device__ __forceinline__ float fold2(unsigned long long v) {
    float lo, hi;
    asm("mov.b64 {%0,%1}, %2;" : "=f"(lo), "=f"(hi) : "l"(v));
    return lo + hi;
}

__device__ __forceinline__ float sigmoid_(float v) {
    float e = __expf(-v);
    return __fdividef(1.f, 1.f + e);
}
__device__ __forceinline__ float tanh_(float v) {
    float e = __expf(2.f * v);
    return __fdividef(e - 1.f, e + 1.f);
}

// ---------------- flag primitives ----------------
__device__ __forceinline__ void warp_arrive(unsigned* c) {
    asm volatile("red.release.gpu.global.add.u32 [%0], %1;" :: "l"(c), "r"(1u) : "memory");
}
__device__ __forceinline__ void poll_ge(const unsigned* f, unsigned need) {
    unsigned v;
    do {
        asm volatile("ld.acquire.gpu.global.u32 %0, [%1];" : "=r"(v) : "l"(f) : "memory");
    } while (v < need);
}

// ================= projection GEMM (proven, ~571us) =================
__global__ __launch_bounds__(256) void proj_kernel(
    const float* __restrict__ x,
    const float* __restrict__ Wz, const float* __restrict__ Wr, const float* __restrict__ Wh,
    const float* __restrict__ bz, const float* __restrict__ br, const float* __restrict__ bh)
{
    __shared__ float As[32 * 132];
    __shared__ float Bs[32 * 64];

    const int g = blockIdx.z;
    const float* W    = (g == 0) ? Wz : (g == 1) ? Wr : Wh;
    const float* bias = (g == 0) ? bz : (g == 1) ? br : bh;
    float* out = g_xp + (size_t)g * MH;

    const int mtile = blockIdx.x * 128;
    const int ntile = blockIdx.y * 64;
    const int tid = threadIdx.x;
    const int tm = tid >> 4;
    const int tn = tid & 15;

    float acc[8][4] = {};

    for (int kc = 0; kc < 128; kc += 32) {
        __syncthreads();
        #pragma unroll
        for (int it = 0; it < 4; ++it) {
            int idx = tid + it * 256;
            int m = idx >> 3, c4 = idx & 7;
            float4 v = *(const float4*)&x[(size_t)(mtile + m) * 128 + kc + c4 * 4];
            As[(c4 * 4 + 0) * 132 + m] = v.x;
            As[(c4 * 4 + 1) * 132 + m] = v.y;
            As[(c4 * 4 + 2) * 132 + m] = v.z;
            As[(c4 * 4 + 3) * 132 + m] = v.w;
        }
        #pragma unroll
        for (int it = 0; it < 2; ++it) {
            int idx = tid + it * 256;
            int kk = idx >> 4, n4 = idx & 15;
            float4 v = *(const float4*)&W[(size_t)(kc + kk) * 256 + ntile + n4 * 4];
            *(float4*)&Bs[kk * 64 + n4 * 4] = v;
        }
        __syncthreads();

        #pragma unroll
        for (int kk = 0; kk < 32; ++kk) {
            float4 a0 = *(const float4*)&As[kk * 132 + tm * 8];
            float4 a1 = *(const float4*)&As[kk * 132 + tm * 8 + 4];
            float4 bv = *(const float4*)&Bs[kk * 64 + tn * 4];
            float a[8] = {a0.x, a0.y, a0.z, a0.w, a1.x, a1.y, a1.z, a1.w};
            #pragma unroll
            for (int i = 0; i < 8; i++) {
                acc[i][0] += a[i] * bv.x;
                acc[i][1] += a[i] * bv.y;
                acc[i][2] += a[i] * bv.z;
                acc[i][3] += a[i] * bv.w;
            }
        }
    }

    float4 bb = *(const float4*)&bias[ntile + tn * 4];
    #pragma unroll
    for (int i = 0; i < 8; i++) {
        float4 o = make_float4(acc[i][0] + bb.x, acc[i][1] + bb.y,
                               acc[i][2] + bb.z, acc[i][3] + bb.w);
        *(float4*)&out[(size_t)(mtile + tm * 8 + i) * 256 + ntile + tn * 4] = o;
    }
}

// ================= reset: zero counters + g_h buffer 0 =================
__global__ void reset_kernel() {
    int i = blockIdx.x * 256 + threadIdx.x;
    if (i < NBG * NB * H_) ((float*)g_h)[i] = 0.f;
    if (i < NBG * NC * 32) {
        ((unsigned*)g_cnt_rh)[i] = 0;
        ((unsigned*)g_cnt_h)[i]  = 0;
    }
}

// ================= persistent recurrent scan =================
// R7 structure + per-warp flag arrivals, 3 CTA barriers/step, red_r parity
// double-buffer, x-prefetch into SEPARATE regs (committed at loop tail).
__global__ __launch_bounds__(256, 1) void scan_kernel(
    const float* __restrict__ Uz, const float* __restrict__ Ur, const float* __restrict__ Uh,
    const float* __restrict__ hdecay, float* __restrict__ out)
{
    extern __shared__ float sm[];
    float* asm_h  = sm;                                                // [16][256] 16KB
    float* asm_rh = sm + 4096;                                         // [16][256] 16KB
    unsigned long long* red_z  = (unsigned long long*)(sm + 8192);     // [8][16][32] 32KB
    unsigned long long* red_r0 = (unsigned long long*)(sm + 16384);    // 32KB (parity 0)
    unsigned long long* red_r1 = (unsigned long long*)(sm + 24576);    // 32KB (parity 1)

    const int tid = threadIdx.x;
    const int w = tid >> 5;          // warp -> k block [32w,32w+32), source CTA w
    const int l = tid & 31;
    const int grp = blockIdx.x >> 3;
    const int cg  = blockIdx.x & 7;
    const int j = cg * HC + l;
    const int b0g = grp * NB;

    // weights: packed f32x2 over k-pairs
    unsigned long long uz2[16], ur2[16], uh2[16];
    #pragma unroll
    for (int p = 0; p < 16; ++p) {
        int k = w * 32 + 2 * p;
        uz2[p] = pack2(Uz[(size_t)k * H_ + j], Uz[(size_t)(k + 1) * H_ + j]);
        ur2[p] = pack2(Ur[(size_t)k * H_ + j], Ur[(size_t)(k + 1) * H_ + j]);
        uh2[p] = pack2(Uh[(size_t)k * H_ + j], Uh[(size_t)(k + 1) * H_ + j]);
    }

    const unsigned* frh = &g_cnt_rh[grp][w][0];   // source CTA w's counters
    const unsigned* fh  = &g_cnt_h [grp][w][0];
    unsigned* myfrh = &g_cnt_rh[grp][cg][0];      // own counters
    unsigned* myfh  = &g_cnt_h [grp][cg][0];

    // gather mapping: lane l -> row l>>1, float4 block (l&1)*4 .. +3
    const int gr = l >> 1;
    const int gh = (l & 1) * 4;

    // x projections for t=0
    size_t mb0 = (size_t)(b0g + w) * T_;
    size_t mb1 = (size_t)(b0g + w + 8) * T_;
    float xz0 = g_xp[mb0 * 256 + j],          xz1 = g_xp[mb1 * 256 + j];
    float xr0 = g_xp[MH + mb0 * 256 + j],     xr1 = g_xp[MH + mb1 * 256 + j];
    float xh0 = g_xp[2 * MH + mb0 * 256 + j], xh1 = g_xp[2 * MH + mb1 * 256 + j];

    for (int t = 0; t < T_; ++t) {
        const int p = t & 1;
        unsigned long long* red_r = p ? red_r1 : red_r0;
        const size_t m0 = (size_t)(b0g + w) * T_ + t;
        const size_t m1 = (size_t)(b0g + w + 8) * T_ + t;
        const bool more = (t + 1 < T_);

        float decn0 = 0.f, decn1 = 0.f;
        if (more) { decn0 = hdecay[m0 + 1]; decn1 = hdecay[m1 + 1]; }

        // ---- A: wait for source CTA w's h, gather slice into smem ----
        poll_ge(fh, 8u * (unsigned)t);
        {
            const float4* src = (const float4*)&g_h[p][grp][gr][w * 32 + gh * 4];
            float4 v0 = __ldcg(src + 0), v1 = __ldcg(src + 1);
            float4 v2 = __ldcg(src + 2), v3 = __ldcg(src + 3);
            float4* dst = (float4*)&asm_h[gr * 256 + w * 32 + gh * 4];
            dst[0] = v0; dst[1] = v1; dst[2] = v2; dst[3] = v3;
        }
        __syncwarp();

        // ---- B: merged z+r GEMM (one pass over asm_h) ----
        #pragma unroll 1
        for (int b = 0; b < NB; ++b) {
            unsigned long long az0 = 0, az1 = 0, ar0 = 0, ar1 = 0;
            const float* hrow = &asm_h[b * 256 + w * 32];
            #pragma unroll
            for (int q = 0; q < 8; ++q) {
                ulonglong2 hv = *(const ulonglong2*)(hrow + q * 4);
                fma2(az0, hv.x, uz2[2 * q]);
                fma2(az1, hv.y, uz2[2 * q + 1]);
                fma2(ar0, hv.x, ur2[2 * q]);
                fma2(ar1, hv.y, ur2[2 * q + 1]);
            }
            red_z[(w * 16 + b) * 32 + l] = add2(az0, az1);
            red_r[(w * 16 + b) * 32 + l] = add2(ar0, ar1);
        }
        __syncthreads();   // S1: partials + all h staging visible CTA-wide

        // ---- C: r reduce, publish rh rows {w, w+8}, per-warp arrive ----
        float hd0, hd1;
        {
            unsigned long long s0 = 0, s1 = 0;
            #pragma unroll
            for (int ww = 0; ww < 8; ++ww) {
                s0 = add2(s0, red_r[(ww * 16 + w) * 32 + l]);
                s1 = add2(s1, red_r[(ww * 16 + w + 8) * 32 + l]);
            }
            float r0 = sigmoid_(fold2(s0) + xr0);
            float r1 = sigmoid_(fold2(s1) + xr1);
            hd0 = asm_h[w * 256 + j];
            hd1 = asm_h[(w + 8) * 256 + j];
            __stcg(&g_rh[p][grp][w][j],     r0 * hd0);
            __stcg(&g_rh[p][grp][w + 8][j], r1 * hd1);
        }
        __syncwarp();
        if (l == 0) warp_arrive(myfrh);

        // ---- D: z reduce + x prefetch into temporaries (fills rh window) ----
        float zv0, zv1;
        float nxz0 = 0.f, nxz1 = 0.f, nxr0 = 0.f, nxr1 = 0.f, nxh0 = 0.f, nxh1 = 0.f;
        {
            unsigned long long s0 = 0, s1 = 0;
            #pragma unroll
            for (int ww = 0; ww < 8; ++ww) {
                s0 = add2(s0, red_z[(ww * 16 + w) * 32 + l]);
                s1 = add2(s1, red_z[(ww * 16 + w + 8) * 32 + l]);
            }
            zv0 = sigmoid_(fold2(s0) + xz0);
            zv1 = sigmoid_(fold2(s1) + xz1);
        }
        if (more) {   // temporaries — old xh/xr/xz stay intact for H below
            nxz0 = g_xp[(m0 + 1) * 256 + j];          nxz1 = g_xp[(m1 + 1) * 256 + j];
            nxr0 = g_xp[MH + (m0 + 1) * 256 + j];     nxr1 = g_xp[MH + (m1 + 1) * 256 + j];
            nxh0 = g_xp[2 * MH + (m0 + 1) * 256 + j]; nxh1 = g_xp[2 * MH + (m1 + 1) * 256 + j];
        }
        __syncthreads();   // S2: C/D cross-warp reads of red_r/red_z complete

        // ---- E: wait for source CTA w's rh, gather slice ----
        poll_ge(frh, 8u * (unsigned)(t + 1));
        {
            const float4* src = (const float4*)&g_rh[p][grp][gr][w * 32 + gh * 4];
            float4 v0 = __ldcg(src + 0), v1 = __ldcg(src + 1);
            float4 v2 = __ldcg(src + 2), v3 = __ldcg(src + 3);
            float4* dst = (float4*)&asm_rh[gr * 256 + w * 32 + gh * 4];
            dst[0] = v0; dst[1] = v1; dst[2] = v2; dst[3] = v3;
        }
        __syncwarp();

        // ---- F: h GEMM (overwrites red_r[p]; safe past S2) ----
        #pragma unroll 1
        for (int b = 0; b < NB; ++b) {
            unsigned long long ah0 = 0, ah1 = 0;
            const float* hrow = &asm_rh[b * 256 + w * 32];
            #pragma unroll
            for (int q = 0; q < 8; ++q) {
                ulonglong2 hv = *(const ulonglong2*)(hrow + q * 4);
                fma2(ah0, hv.x, uh2[2 * q]);
                fma2(ah1, hv.y, uh2[2 * q + 1]);
            }
            red_r[(w * 16 + b) * 32 + l] = add2(ah0, ah1);
        }
        __syncthreads();   // S3

        // ---- H: h reduce, combine, publish pre-decayed h, per-warp arrive ----
        float h0, h1;
        {
            unsigned long long s0 = 0, s1 = 0;
            #pragma unroll
            for (int ww = 0; ww < 8; ++ww) {
                s0 = add2(s0, red_r[(ww * 16 + w) * 32 + l]);
                s1 = add2(s1, red_r[(ww * 16 + w + 8) * 32 + l]);
            }
            float hp0 = tanh_(fold2(s0) + xh0);
            float hp1 = tanh_(fold2(s1) + xh1);
            h0 = (1.f - zv0) * hd0 + zv0 * hp0;
            h1 = (1.f - zv1) * hd1 + zv1 * hp1;
            if (more) {
                __stcg(&g_h[(t + 1) & 1][grp][w][j],     h0 * decn0);
                __stcg(&g_h[(t + 1) & 1][grp][w + 8][j], h1 * decn1);
            }
        }
        __syncwarp();
        if (more && l == 0) warp_arrive(myfh);

        // ---- I: outputs + commit prefetched x (off critical path) ----
        out[m0 * 256 + j] = h0;
        out[m1 * 256 + j] = h1;
        xz0 = nxz0; xz1 = nxz1;
        xr0 = nxr0; xr1 = nxr1;
        xh0 = nxh0; xh1 = nxh1;
    }
}

// ================= launch =================
extern "C" void kernel_launch(void* const* d_in, const int* /*in_sizes*/, int /*n_in*/,
                              void* d_out, int /*out_size*/)
{
    const float* x      = (const float*)d_in[0];
    const float* hdecay = (const float*)d_in[1];
    const float* Wr = (const float*)d_in[2];
    const float* Wz = (const float*)d_in[3];
    const float* Wh = (const float*)d_in[4];
    const float* Ur = (const float*)d_in[5];
    const float* Uz = (const float*)d_in[6];
    const float* Uh = (const float*)d_in[7];
    const float* br = (const float*)d_in[8];
    const float* bz = (const float*)d_in[9];
    const float* bh = (const float*)d_in[10];
    float* out = (float*)d_out;

    constexpr int SMEM_SCAN = 32768 * 4;   // 128KB dynamic
    cudaFuncSetAttribute(scan_kernel, cudaFuncAttributeMaxDynamicSharedMemorySize, SMEM_SCAN);

    proj_kernel<<<dim3(MTOT / 128, H_ / 64, 3), 256>>>(x, Wz, Wr, Wh, bz, br, bh);
    reset_kernel<<<256, 256>>>();
    scan_kernel<<<NBG * NC, 256, SMEM_SCAN>>>(Uz, Ur, Uh, hdecay, out);
}